// round 11
// baseline (speedup 1.0000x reference)
#include <cuda_runtime.h>
#include <cuda_fp16.h>
#include <math.h>

#define NB 512
#define HOR 12

// D quantization: fixed scale, qD = round(D/FS), |D| clamp at 0.25
#define FS_D (0.25f/127.f)

// output layout (floats): I_sim, E_sim, beta.mean, sigma.mean, gamma.mean, Pi.mean
#define OUT_I  0
#define OUT_E  (NB*HOR*256)
#define OUT_BM (2*NB*HOR*256)
#define OUT_PI (OUT_BM + 768)
#define OUT_ZN (768 + 65536)

__device__ float g_hsum[NB*128];                 // param hidden accum (pre-zeroed)
__device__ float g_beta[NB*256];
__device__ float g_sigma[NB*256];
__device__ float g_gamma[NB*256];
__device__ float g_e0[NB*256];
__device__ __align__(16) signed char g_D8[(size_t)NB*256*256];  // int8 D, [b][n][m]
__device__ unsigned g_qh[NB*32];                 // int8-packed hm rows
__device__ float g_sh[NB];                       // hm row scales
__device__ __align__(16) unsigned g_qm[(size_t)256*8192];  // int8 M2, [icol][q][j]
__device__ float g_sm[65536];                    // M2 column scales

// ---------- K3c: quantize M2 per output column + zero out-means region ----------
__global__ __launch_bounds__(256) void k3c(const float* __restrict__ M2,
                                           float* out) {
    int j = threadIdx.x, icol = blockIdx.x;
    int idx = icol*256 + j;
    out[OUT_BM + idx] = 0.f;
    if (idx < 768) out[OUT_BM + 65536 + idx] = 0.f;
    const float* base = M2 + (size_t)icol*256 + j;
    float mx = 0.f;
    #pragma unroll 8
    for (int k = 0; k < 128; ++k) mx = fmaxf(mx, fabsf(base[(size_t)k*65536]));
    float inv = mx > 0.f ? 127.f/mx : 0.f;
    g_sm[icol*256 + j] = mx * (1.f/127.f);
    for (int q = 0; q < 32; ++q) {
        unsigned w = 0;
        #pragma unroll
        for (int e = 0; e < 4; ++e) {
            float v = base[(size_t)(4*q + e)*65536];
            int qi = __float2int_rn(v*inv);
            qi = max(-127, min(127, qi));
            w |= ((unsigned)(qi & 255)) << (8*e);
        }
        g_qm[(size_t)icol*8192 + q*256 + j] = w;
    }
}

// ---------- K3f: hm = relu(cnn @ M1 + mb1) + int8 quantize; zero g_hsum ----------
__global__ __launch_bounds__(256) void k3f(const float* __restrict__ cnn,
                                           const float* __restrict__ M1,
                                           const float* __restrict__ mb1) {
    __shared__ __align__(16) float sa[16*68];
    __shared__ __align__(16) float sw[16*128];
    int t = threadIdx.x, rg = t >> 4, cg = t & 15;
    int B0 = blockIdx.x * 64;
    #pragma unroll
    for (int i = 0; i < 32; ++i)
        g_hsum[(blockIdx.x*256 + t)*32 + i] = 0.f;
    float acc[4][8] = {};
    for (int kt = 0; kt < 4; ++kt) {
        int k0 = kt*16;
        #pragma unroll
        for (int i = t; i < 1024; i += 256) {
            int r = i >> 4, kk = i & 15;
            sa[kk*68 + r] = cnn[(size_t)(B0 + r)*64 + k0 + kk];
        }
        #pragma unroll
        for (int i = t; i < 2048; i += 256) {
            int kk = i >> 7, c = i & 127;
            sw[kk*128 + c] = M1[(size_t)(k0 + kk)*128 + c];
        }
        __syncthreads();
        #pragma unroll
        for (int kk = 0; kk < 16; ++kk) {
            float4 a  = *(const float4*)&sa[kk*68 + rg*4];
            float4 b0 = *(const float4*)&sw[kk*128 + cg*8];
            float4 b1 = *(const float4*)&sw[kk*128 + cg*8 + 4];
            float av[4] = {a.x,a.y,a.z,a.w};
            float bv[8] = {b0.x,b0.y,b0.z,b0.w,b1.x,b1.y,b1.z,b1.w};
            #pragma unroll
            for (int i = 0; i < 4; i++)
                #pragma unroll
                for (int q = 0; q < 8; q++)
                    acc[i][q] = fmaf(av[i], bv[q], acc[i][q]);
        }
        __syncthreads();
    }
    #pragma unroll
    for (int i = 0; i < 4; i++) {
        float h[8];
        float mx = 0.f;
        #pragma unroll
        for (int q = 0; q < 8; q++) {
            h[q] = fmaxf(acc[i][q] + mb1[cg*8 + q], 0.f);
            mx = fmaxf(mx, h[q]);
        }
        #pragma unroll
        for (int o = 1; o < 16; o <<= 1)
            mx = fmaxf(mx, __shfl_xor_sync(0xffffffffu, mx, o));
        float inv = mx > 0.f ? 127.f/mx : 0.f;
        int row = B0 + rg*4 + i;
        unsigned w0 = 0, w1 = 0;
        #pragma unroll
        for (int e = 0; e < 4; ++e) {
            w0 |= ((unsigned)(__float2int_rn(h[e]*inv)   & 255)) << (8*e);
            w1 |= ((unsigned)(__float2int_rn(h[4+e]*inv) & 255)) << (8*e);
        }
        g_qh[row*32 + cg*2]     = w0;
        g_qh[row*32 + cg*2 + 1] = w1;
        if (cg == 0) g_sh[row] = mx * (1.f/127.f);
    }
}

// ---------- K4: int8 IMMA logits + softmax + int8 D + Pi.mean ----------
#define K4_SMEM (13184 * 4)
__global__ __launch_bounds__(256, 2) void k4(const float* __restrict__ mb2,
                                             float* out) {
    extern __shared__ __align__(16) unsigned smu[];
    unsigned* qhS = smu;                 // [64][33]
    unsigned* qmS = smu + 2112;          // [32][260]
    float* smjS = (float*)(smu + 10432); // [256]
    float* mbjS = (float*)(smu + 10688); // [256]
    float* shS  = (float*)(smu + 10944); // [64]
    float* rs   = (float*)(smu + 11008); // [2][64]
    float* psum = (float*)(smu + 11136); // [8][256]
    int t = threadIdx.x;
    int icol = blockIdx.x, B0 = blockIdx.y * 64;
    int w = t >> 5, lane = t & 31;
    int mw = w & 3, nh = w >> 2;
    int r = lane >> 2, c = lane & 3;
    int m0 = mw * 16;

    #pragma unroll
    for (int i = t; i < 2048; i += 256) {
        int b = i >> 5, q = i & 31;
        qhS[b*33 + q] = g_qh[(B0 + b)*32 + q];
    }
    {
        const uint4* src = (const uint4*)(g_qm + (size_t)icol*8192);
        #pragma unroll
        for (int i = t; i < 2048; i += 256) {
            int q = i >> 6, j4 = i & 63;
            *(uint4*)&qmS[q*260 + j4*4] = src[i];
        }
    }
    smjS[t] = g_sm[icol*256 + t];
    mbjS[t] = mb2[(size_t)icol*256 + t];
    if (t < 64) shS[t] = g_sh[B0 + t];
    #pragma unroll
    for (int i = t; i < 2048; i += 256) psum[i] = 0.f;
    __syncthreads();

    int acc[16][4] = {};
    #pragma unroll
    for (int kt = 0; kt < 4; ++kt) {
        int a0 = (int)qhS[(m0 + r)*33     + kt*8 + c];
        int a1 = (int)qhS[(m0 + r + 8)*33 + kt*8 + c];
        int a2 = (int)qhS[(m0 + r)*33     + kt*8 + 4 + c];
        int a3 = (int)qhS[(m0 + r + 8)*33 + kt*8 + 4 + c];
        #pragma unroll
        for (int nt = 0; nt < 16; ++nt) {
            int ncol = nh*128 + nt*8 + r;
            int b0 = (int)qmS[(kt*8 + c)*260 + ncol];
            int b1 = (int)qmS[(kt*8 + 4 + c)*260 + ncol];
            asm volatile(
                "mma.sync.aligned.m16n8k32.row.col.s32.s8.s8.s32 "
                "{%0,%1,%2,%3}, {%4,%5,%6,%7}, {%8,%9}, {%0,%1,%2,%3};"
                : "+r"(acc[nt][0]), "+r"(acc[nt][1]), "+r"(acc[nt][2]), "+r"(acc[nt][3])
                : "r"(a0), "r"(a1), "r"(a2), "r"(a3), "r"(b0), "r"(b1));
        }
    }

    float shA = shS[m0 + r], shB = shS[m0 + r + 8];
    float sA = 0.f, sB = 0.f;
    #pragma unroll
    for (int nt = 0; nt < 16; ++nt) {
        int j0 = nh*128 + nt*8 + 2*c;
        float sj0 = smjS[j0], sj1 = smjS[j0 + 1];
        float m0b = mbjS[j0], m1b = mbjS[j0 + 1];
        float e00 = __expf((float)acc[nt][0] * (shA*sj0) + m0b);
        float e01 = __expf((float)acc[nt][1] * (shA*sj1) + m1b);
        float e10 = __expf((float)acc[nt][2] * (shB*sj0) + m0b);
        float e11 = __expf((float)acc[nt][3] * (shB*sj1) + m1b);
        sA += e00 + e01;  sB += e10 + e11;
        acc[nt][0] = __float_as_int(e00);
        acc[nt][1] = __float_as_int(e01);
        acc[nt][2] = __float_as_int(e10);
        acc[nt][3] = __float_as_int(e11);
    }
    sA += __shfl_xor_sync(0xffffffffu, sA, 1);
    sA += __shfl_xor_sync(0xffffffffu, sA, 2);
    sB += __shfl_xor_sync(0xffffffffu, sB, 1);
    sB += __shfl_xor_sync(0xffffffffu, sB, 2);
    if (c == 0) {
        rs[nh*64 + m0 + r] = sA;
        rs[nh*64 + m0 + r + 8] = sB;
    }
    __syncthreads();
    float invA = 1.f / (rs[m0 + r] + rs[64 + m0 + r]);
    float invB = 1.f / (rs[m0 + r + 8] + rs[64 + m0 + r + 8]);

    signed char* dpA = g_D8 + (size_t)(B0 + m0 + r)*65536 + icol*256;
    signed char* dpB = g_D8 + (size_t)(B0 + m0 + r + 8)*65536 + icol*256;
    const float qsc = 1.f / FS_D;
    #pragma unroll
    for (int nt = 0; nt < 16; ++nt) {
        int j0 = nh*128 + nt*8 + 2*c;
        float pA0 = __int_as_float(acc[nt][0]) * invA;
        float pA1 = __int_as_float(acc[nt][1]) * invA;
        float pB0 = __int_as_float(acc[nt][2]) * invB;
        float pB1 = __int_as_float(acc[nt][3]) * invB;
        int qa0 = min(127, max(-127, __float2int_rn(fmaf(pA0, 256.f, -1.f) * qsc)));
        int qa1 = min(127, max(-127, __float2int_rn(fmaf(pA1, 256.f, -1.f) * qsc)));
        int qb0 = min(127, max(-127, __float2int_rn(fmaf(pB0, 256.f, -1.f) * qsc)));
        int qb1 = min(127, max(-127, __float2int_rn(fmaf(pB1, 256.f, -1.f) * qsc)));
        *(char2*)(dpA + j0) = make_char2((signed char)qa0, (signed char)qa1);
        *(char2*)(dpB + j0) = make_char2((signed char)qb0, (signed char)qb1);
        float pm0 = pA0 + pB0, pm1 = pA1 + pB1;
        pm0 += __shfl_xor_sync(0xffffffffu, pm0, 4);
        pm0 += __shfl_xor_sync(0xffffffffu, pm0, 8);
        pm0 += __shfl_xor_sync(0xffffffffu, pm0, 16);
        pm1 += __shfl_xor_sync(0xffffffffu, pm1, 4);
        pm1 += __shfl_xor_sync(0xffffffffu, pm1, 8);
        pm1 += __shfl_xor_sync(0xffffffffu, pm1, 16);
        if (r == 0) {
            psum[w*256 + j0] = pm0;
            psum[w*256 + j0 + 1] = pm1;
        }
    }
    __syncthreads();
    float s2 = 0.f;
    #pragma unroll
    for (int g = 0; g < 8; g++) s2 += psum[g*256 + t];
    atomicAdd(&out[OUT_PI + icol*256 + t], s2 * (1.f/512.f));
}

// ---------- K1: g_hsum += x @ W1 chunk (tile 128x128, 32 k-splits, atomics) ----------
__global__ __launch_bounds__(256) void k1(const float* __restrict__ x,
                                          const float* __restrict__ W1) {
    __shared__ __align__(16) float sa[16*132];
    __shared__ __align__(16) float sw[16*128];
    int t = threadIdx.x, rg = t >> 4, cg = t & 15;
    int B0 = blockIdx.x * 128, kz = blockIdx.y;
    float acc[8][8] = {};
    for (int kt = 0; kt < 8; ++kt) {
        int k0 = kz*128 + kt*16;
        #pragma unroll
        for (int i = t; i < 512; i += 256) {
            int r = i >> 2, kq = i & 3;
            float4 v = *(const float4*)&x[(size_t)(B0 + r)*4096 + k0 + kq*4];
            sa[(kq*4+0)*132 + r] = v.x;
            sa[(kq*4+1)*132 + r] = v.y;
            sa[(kq*4+2)*132 + r] = v.z;
            sa[(kq*4+3)*132 + r] = v.w;
        }
        #pragma unroll
        for (int i = t; i < 512; i += 256) {
            int kk = i >> 5, c4 = i & 31;
            *(float4*)&sw[kk*128 + c4*4] =
                *(const float4*)&W1[(size_t)(k0 + kk)*128 + c4*4];
        }
        __syncthreads();
        #pragma unroll
        for (int kk = 0; kk < 16; ++kk) {
            float4 a0 = *(const float4*)&sa[kk*132 + rg*8];
            float4 a1 = *(const float4*)&sa[kk*132 + rg*8 + 4];
            float4 b0 = *(const float4*)&sw[kk*128 + cg*8];
            float4 b1 = *(const float4*)&sw[kk*128 + cg*8 + 4];
            float av[8] = {a0.x,a0.y,a0.z,a0.w,a1.x,a1.y,a1.z,a1.w};
            float bv[8] = {b0.x,b0.y,b0.z,b0.w,b1.x,b1.y,b1.z,b1.w};
            #pragma unroll
            for (int i = 0; i < 8; i++)
                #pragma unroll
                for (int q = 0; q < 8; q++)
                    acc[i][q] = fmaf(av[i], bv[q], acc[i][q]);
        }
        __syncthreads();
    }
    #pragma unroll
    for (int i = 0; i < 8; i++) {
        int r = B0 + rg*8 + i;
        #pragma unroll
        for (int q = 0; q < 8; q++)
            atomicAdd(&g_hsum[r*128 + cg*8 + q], acc[i][q]);
    }
}

// ---------- K2f: h = relu(g_hsum + b1); params = h @ W2 + b2 ----------
__global__ __launch_bounds__(256) void k2f(const float* __restrict__ b1,
                                           const float* __restrict__ W2,
                                           const float* __restrict__ b2,
                                           float* out) {
    __shared__ __align__(16) float sa[16*68];
    __shared__ __align__(16) float sw[16*128];
    int t = threadIdx.x, rg = t >> 4, cg = t & 15;
    int C0 = blockIdx.x * 128, B0 = blockIdx.y * 64;
    float acc[4][8] = {};
    for (int kt = 0; kt < 8; ++kt) {
        int k0 = kt*16;
        #pragma unroll
        for (int i = t; i < 1024; i += 256) {
            int r = i >> 4, kk = i & 15;
            float s = g_hsum[(B0 + r)*128 + k0 + kk] + b1[k0 + kk];
            sa[kk*68 + r] = fmaxf(s, 0.f);
        }
        #pragma unroll
        for (int i = t; i < 512; i += 256) {
            int kk = i >> 5, c4 = i & 31;
            *(float4*)&sw[kk*128 + c4*4] =
                *(const float4*)&W2[(size_t)(k0 + kk)*1024 + C0 + c4*4];
        }
        __syncthreads();
        #pragma unroll
        for (int kk = 0; kk < 16; ++kk) {
            float4 a  = *(const float4*)&sa[kk*68 + rg*4];
            float4 b0 = *(const float4*)&sw[kk*128 + cg*8];
            float4 b1v = *(const float4*)&sw[kk*128 + cg*8 + 4];
            float av[4] = {a.x,a.y,a.z,a.w};
            float bv[8] = {b0.x,b0.y,b0.z,b0.w,b1v.x,b1v.y,b1v.z,b1v.w};
            #pragma unroll
            for (int i = 0; i < 4; i++)
                #pragma unroll
                for (int q = 0; q < 8; q++)
                    acc[i][q] = fmaf(av[i], bv[q], acc[i][q]);
        }
        __syncthreads();
    }
    int grp = C0 >> 8;
    float scl = (grp == 0) ? 3.f : (grp == 3) ? 5.f : 1.f;
    float* dst = (grp == 0) ? g_beta : (grp == 1) ? g_sigma : (grp == 2) ? g_gamma : g_e0;
    #pragma unroll
    for (int i = 0; i < 4; i++) {
        int rb = B0 + rg*4 + i;
        #pragma unroll
        for (int q = 0; q < 8; q++) {
            int cgg = C0 + cg*8 + q;
            float s = scl / (1.f + __expf(-(acc[i][q] + b2[cgg])));
            int col = cgg & 255;
            dst[rb*256 + col] = s;
            if (grp < 3) atomicAdd(&out[OUT_BM + grp*256 + col], s * (1.f/512.f));
        }
    }
}

// ---------- K5: RK4 SEIR sim, 48 reg + 16 smem D words, occupancy 3 ----------
__global__ __launch_bounds__(256, 3) void k5(const float* __restrict__ x,
                                             float* __restrict__ out) {
    __shared__ float red[2][8];
    __shared__ __align__(16) unsigned Ipk[2][64];
    __shared__ __align__(16) uint4 Dex[4][256];   // words 48..63 per thread (16 KB)
    int t = threadIdx.x, b = blockIdx.x;
    int lane = t & 31, warp = t >> 5;

    unsigned qw[48];
    int Cq = 0;
    {
        const signed char* Ds = g_D8 + (size_t)b*65536 + t;
        #pragma unroll
        for (int g = 0; g < 48; ++g) {
            int b0 = (int)__ldg(Ds + (size_t)(g*4 + 0)*256);
            int b1 = (int)__ldg(Ds + (size_t)(g*4 + 1)*256);
            int b2 = (int)__ldg(Ds + (size_t)(g*4 + 2)*256);
            int b3 = (int)__ldg(Ds + (size_t)(g*4 + 3)*256);
            unsigned w = (unsigned)(b0 & 255) | ((unsigned)(b1 & 255) << 8) |
                         ((unsigned)(b2 & 255) << 16) | ((unsigned)(b3 & 255) << 24);
            qw[g] = w;
            Cq = __dp4a((int)w, 0x01010101, Cq);
        }
        #pragma unroll
        for (int q4 = 0; q4 < 4; ++q4) {
            unsigned wv[4];
            #pragma unroll
            for (int e = 0; e < 4; ++e) {
                int g = 48 + q4*4 + e;
                int b0 = (int)__ldg(Ds + (size_t)(g*4 + 0)*256);
                int b1 = (int)__ldg(Ds + (size_t)(g*4 + 1)*256);
                int b2 = (int)__ldg(Ds + (size_t)(g*4 + 2)*256);
                int b3 = (int)__ldg(Ds + (size_t)(g*4 + 3)*256);
                unsigned w = (unsigned)(b0 & 255) | ((unsigned)(b1 & 255) << 8) |
                             ((unsigned)(b2 & 255) << 16) | ((unsigned)(b3 & 255) << 24);
                wv[e] = w;
                Cq = __dp4a((int)w, 0x01010101, Cq);
            }
            Dex[q4][t] = make_uint4(wv[0], wv[1], wv[2], wv[3]);
        }
    }
    float Cm = (float)Cq * FS_D;
    const float fscale = FS_D * (1.f/127.f);

    float beta = g_beta[b*256 + t], sg = g_sigma[b*256 + t];
    float gm   = g_gamma[b*256 + t], e0r = g_e0[b*256 + t];
    float I = fmaxf(x[(size_t)b*4096 + 15*256 + t], 1e-6f);
    float E = I * e0r;
    float S = fmaxf(1.f - E - I, 0.01f);
    __syncthreads();   // Dex visible to all (own writes only, but keep ordering clean)

    int ec = 0;
    auto force = [&](float Iv) -> float {
        int buf = ec & 1;  ec ^= 1;
        ((signed char*)Ipk[buf])[t] = (signed char)__float2int_rn((Iv - 0.5f) * 127.f);
        float s = Iv;
        #pragma unroll
        for (int o = 16; o > 0; o >>= 1) s += __shfl_xor_sync(0xffffffffu, s, o);
        if (lane == 0) red[buf][warp] = s;
        __syncthreads();
        float sumI = red[buf][0]+red[buf][1]+red[buf][2]+red[buf][3]
                   + red[buf][4]+red[buf][5]+red[buf][6]+red[buf][7];
        int a0 = 0, a1 = 0, a2 = 0, a3 = 0;
        const unsigned* ip = Ipk[buf];
        #pragma unroll
        for (int g = 0; g < 48; g += 4) {
            uint4 wv = *(const uint4*)&ip[g];
            a0 = __dp4a((int)wv.x, (int)qw[g+0], a0);
            a1 = __dp4a((int)wv.y, (int)qw[g+1], a1);
            a2 = __dp4a((int)wv.z, (int)qw[g+2], a2);
            a3 = __dp4a((int)wv.w, (int)qw[g+3], a3);
        }
        #pragma unroll
        for (int q4 = 0; q4 < 4; ++q4) {
            uint4 dv = Dex[q4][t];
            uint4 wv = *(const uint4*)&ip[48 + q4*4];
            a0 = __dp4a((int)wv.x, (int)dv.x, a0);
            a1 = __dp4a((int)wv.y, (int)dv.y, a1);
            a2 = __dp4a((int)wv.z, (int)dv.z, a2);
            a3 = __dp4a((int)wv.w, (int)dv.w, a3);
        }
        float resid = (float)(a0 + a1 + a2 + a3) * fscale;
        return (sumI + 0.5f * Cm + resid) * (1.f/256.f);
    };

    for (int w = 0; w < HOR; ++w) {
        for (int st = 0; st < 4; ++st) {
            float f1 = force(I);
            float ni = beta * S * f1;
            float dS1 = -ni, dE1 = ni - sg*E, dI1 = sg*E - gm*I;
            float S2 = S + 0.125f*dS1, E2 = E + 0.125f*dE1, I2 = I + 0.125f*dI1;
            float f2 = force(I2); ni = beta * S2 * f2;
            float dS2 = -ni, dE2 = ni - sg*E2, dI2 = sg*E2 - gm*I2;
            float S3 = S + 0.125f*dS2, E3 = E + 0.125f*dE2, I3 = I + 0.125f*dI2;
            float f3 = force(I3); ni = beta * S3 * f3;
            float dS3 = -ni, dE3 = ni - sg*E3, dI3 = sg*E3 - gm*I3;
            float S4 = S + 0.25f*dS3, E4 = E + 0.25f*dE3, I4 = I + 0.25f*dI3;
            float f4 = force(I4); ni = beta * S4 * f4;
            float dS4 = -ni, dE4 = ni - sg*E4, dI4 = sg*E4 - gm*I4;
            const float c = 0.25f / 6.f;
            S = fminf(fmaxf(S + c*(dS1 + 2.f*dS2 + 2.f*dS3 + dS4), 0.f), 1.f);
            E = fminf(fmaxf(E + c*(dE1 + 2.f*dE2 + 2.f*dE3 + dE4), 0.f), 1.f);
            I = fminf(fmaxf(I + c*(dI1 + 2.f*dI2 + 2.f*dI3 + dI4), 0.f), 1.f);
        }
        out[OUT_I + ((size_t)b*HOR + w)*256 + t] = I;
        out[OUT_E + ((size_t)b*HOR + w)*256 + t] = E;
    }
}

extern "C" void kernel_launch(void* const* d_in, const int* in_sizes, int n_in,
                              void* d_out, int out_size) {
    const float* x    = (const float*)d_in[0];
    const float* cnn  = (const float*)d_in[1];
    const float* W1   = (const float*)d_in[2];
    const float* b1   = (const float*)d_in[3];
    const float* W2   = (const float*)d_in[4];
    const float* b2   = (const float*)d_in[5];
    const float* M1   = (const float*)d_in[6];
    const float* mb1  = (const float*)d_in[7];
    const float* M2   = (const float*)d_in[8];
    const float* mb2  = (const float*)d_in[9];
    float* out = (float*)d_out;

    static cudaStream_t s2 = nullptr;
    static cudaEvent_t evA = nullptr, evB = nullptr, evD = nullptr, evZ = nullptr;
    if (!s2) {
        cudaStreamCreateWithFlags(&s2, cudaStreamNonBlocking);
        cudaEventCreateWithFlags(&evA, cudaEventDisableTiming);
        cudaEventCreateWithFlags(&evB, cudaEventDisableTiming);
        cudaEventCreateWithFlags(&evD, cudaEventDisableTiming);
        cudaEventCreateWithFlags(&evZ, cudaEventDisableTiming);
        cudaFuncSetAttribute(k4, cudaFuncAttributeMaxDynamicSharedMemorySize, K4_SMEM);
    }

    // s2: M2 quantization + output zeroing
    cudaEventRecord(evA, 0);
    cudaStreamWaitEvent(s2, evA, 0);
    k3c<<<256, 256, 0, s2>>>(M2, out);
    cudaEventRecord(evZ, s2);

    // main: mobility hidden + quantize + zero g_hsum
    k3f<<<8, 256>>>(cnn, M1, mb1);
    cudaEventRecord(evB, 0);

    // s2: IMMA softmax + int8 D
    cudaStreamWaitEvent(s2, evB, 0);
    k4<<<dim3(256, 8), 256, K4_SMEM, s2>>>(mb2, out);
    cudaEventRecord(evD, s2);

    // main: param branch (concurrent with k4)
    k1<<<dim3(4, 32), 256>>>(x, W1);
    cudaStreamWaitEvent(0, evZ, 0);
    k2f<<<dim3(8, 8), 256>>>(b1, W2, b2, out);

    // join, then sim
    cudaStreamWaitEvent(0, evD, 0);
    k5<<<512, 256>>>(x, out);
}

// round 12
// speedup vs baseline: 1.3115x; 1.3115x over previous
#include <cuda_runtime.h>
#include <cuda_fp16.h>
#include <math.h>

#define NB 512
#define HOR 12

// D quantization: fixed scale, qD = round(D/FS), |D| clamp at 0.25
#define FS_D (0.25f/127.f)

// output layout (floats): I_sim, E_sim, beta.mean, sigma.mean, gamma.mean, Pi.mean
#define OUT_I  0
#define OUT_E  (NB*HOR*256)
#define OUT_BM (2*NB*HOR*256)
#define OUT_PI (OUT_BM + 768)

__device__ float g_hsum[NB*128];                 // param hidden accum (pre-zeroed)
__device__ __align__(16) signed char g_D8[(size_t)NB*256*256];  // int8 D, [b][n][m]
__device__ unsigned g_qh[NB*32];                 // int8-packed hm rows
__device__ float g_sh[NB];                       // hm row scales
__device__ __align__(16) unsigned g_qm[(size_t)256*8192];  // int8 M2, [icol][q][j]
__device__ float g_sm[65536];                    // M2 column scales

// ---------- kA: fused  [blocks 0..255] M2 quant + zero out-means
//                       [blocks 256..263] mobility hidden GEMM + quantize + zero g_hsum
__global__ __launch_bounds__(256) void kA(const float* __restrict__ M2,
                                          const float* __restrict__ cnn,
                                          const float* __restrict__ M1,
                                          const float* __restrict__ mb1,
                                          float* out) {
    __shared__ __align__(16) float sa[16*68];
    __shared__ __align__(16) float sw[16*128];
    int t = threadIdx.x;
    if (blockIdx.x < 256) {
        // ---- k3c body ----
        int icol = blockIdx.x, j = t;
        int idx = icol*256 + j;
        out[OUT_BM + idx] = 0.f;
        if (idx < 768) out[OUT_BM + 65536 + idx] = 0.f;
        const float* base = M2 + (size_t)icol*256 + j;
        float mx = 0.f;
        #pragma unroll 8
        for (int k = 0; k < 128; ++k) mx = fmaxf(mx, fabsf(base[(size_t)k*65536]));
        float inv = mx > 0.f ? 127.f/mx : 0.f;
        g_sm[icol*256 + j] = mx * (1.f/127.f);
        for (int q = 0; q < 32; ++q) {
            unsigned w = 0;
            #pragma unroll
            for (int e = 0; e < 4; ++e) {
                float v = base[(size_t)(4*q + e)*65536];
                int qi = __float2int_rn(v*inv);
                qi = max(-127, min(127, qi));
                w |= ((unsigned)(qi & 255)) << (8*e);
            }
            g_qm[(size_t)icol*8192 + q*256 + j] = w;
        }
        return;
    }
    // ---- k3f body ----
    int blk = blockIdx.x - 256;
    int rg = t >> 4, cg = t & 15;
    int B0 = blk * 64;
    #pragma unroll
    for (int i = 0; i < 32; ++i)
        g_hsum[(blk*256 + t)*32 + i] = 0.f;
    float acc[4][8] = {};
    for (int kt = 0; kt < 4; ++kt) {
        int k0 = kt*16;
        #pragma unroll
        for (int i = t; i < 1024; i += 256) {
            int r = i >> 4, kk = i & 15;
            sa[kk*68 + r] = cnn[(size_t)(B0 + r)*64 + k0 + kk];
        }
        #pragma unroll
        for (int i = t; i < 2048; i += 256) {
            int kk = i >> 7, c = i & 127;
            sw[kk*128 + c] = M1[(size_t)(k0 + kk)*128 + c];
        }
        __syncthreads();
        #pragma unroll
        for (int kk = 0; kk < 16; ++kk) {
            float4 a  = *(const float4*)&sa[kk*68 + rg*4];
            float4 b0 = *(const float4*)&sw[kk*128 + cg*8];
            float4 b1 = *(const float4*)&sw[kk*128 + cg*8 + 4];
            float av[4] = {a.x,a.y,a.z,a.w};
            float bv[8] = {b0.x,b0.y,b0.z,b0.w,b1.x,b1.y,b1.z,b1.w};
            #pragma unroll
            for (int i = 0; i < 4; i++)
                #pragma unroll
                for (int q = 0; q < 8; q++)
                    acc[i][q] = fmaf(av[i], bv[q], acc[i][q]);
        }
        __syncthreads();
    }
    #pragma unroll
    for (int i = 0; i < 4; i++) {
        float h[8];
        float mx = 0.f;
        #pragma unroll
        for (int q = 0; q < 8; q++) {
            h[q] = fmaxf(acc[i][q] + mb1[cg*8 + q], 0.f);
            mx = fmaxf(mx, h[q]);
        }
        #pragma unroll
        for (int o = 1; o < 16; o <<= 1)
            mx = fmaxf(mx, __shfl_xor_sync(0xffffffffu, mx, o));
        float inv = mx > 0.f ? 127.f/mx : 0.f;
        int row = B0 + rg*4 + i;
        unsigned w0 = 0, w1 = 0;
        #pragma unroll
        for (int e = 0; e < 4; ++e) {
            w0 |= ((unsigned)(__float2int_rn(h[e]*inv)   & 255)) << (8*e);
            w1 |= ((unsigned)(__float2int_rn(h[4+e]*inv) & 255)) << (8*e);
        }
        g_qh[row*32 + cg*2]     = w0;
        g_qh[row*32 + cg*2 + 1] = w1;
        if (cg == 0) g_sh[row] = mx * (1.f/127.f);
    }
}

// ---------- K4: int8 IMMA logits + softmax + int8 D + Pi.mean ----------
#define K4_SMEM (13184 * 4)
__global__ __launch_bounds__(256, 2) void k4(const float* __restrict__ mb2,
                                             float* out) {
    extern __shared__ __align__(16) unsigned smu[];
    unsigned* qhS = smu;                 // [64][33]
    unsigned* qmS = smu + 2112;          // [32][260]
    float* smjS = (float*)(smu + 10432); // [256]
    float* mbjS = (float*)(smu + 10688); // [256]
    float* shS  = (float*)(smu + 10944); // [64]
    float* rs   = (float*)(smu + 11008); // [2][64]
    float* psum = (float*)(smu + 11136); // [8][256]
    int t = threadIdx.x;
    int icol = blockIdx.x, B0 = blockIdx.y * 64;
    int w = t >> 5, lane = t & 31;
    int mw = w & 3, nh = w >> 2;
    int r = lane >> 2, c = lane & 3;
    int m0 = mw * 16;

    #pragma unroll
    for (int i = t; i < 2048; i += 256) {
        int b = i >> 5, q = i & 31;
        qhS[b*33 + q] = g_qh[(B0 + b)*32 + q];
    }
    {
        const uint4* src = (const uint4*)(g_qm + (size_t)icol*8192);
        #pragma unroll
        for (int i = t; i < 2048; i += 256) {
            int q = i >> 6, j4 = i & 63;
            *(uint4*)&qmS[q*260 + j4*4] = src[i];
        }
    }
    smjS[t] = g_sm[icol*256 + t];
    mbjS[t] = mb2[(size_t)icol*256 + t];
    if (t < 64) shS[t] = g_sh[B0 + t];
    #pragma unroll
    for (int i = t; i < 2048; i += 256) psum[i] = 0.f;
    __syncthreads();

    int acc[16][4] = {};
    #pragma unroll
    for (int kt = 0; kt < 4; ++kt) {
        int a0 = (int)qhS[(m0 + r)*33     + kt*8 + c];
        int a1 = (int)qhS[(m0 + r + 8)*33 + kt*8 + c];
        int a2 = (int)qhS[(m0 + r)*33     + kt*8 + 4 + c];
        int a3 = (int)qhS[(m0 + r + 8)*33 + kt*8 + 4 + c];
        #pragma unroll
        for (int nt = 0; nt < 16; ++nt) {
            int ncol = nh*128 + nt*8 + r;
            int b0 = (int)qmS[(kt*8 + c)*260 + ncol];
            int b1 = (int)qmS[(kt*8 + 4 + c)*260 + ncol];
            asm volatile(
                "mma.sync.aligned.m16n8k32.row.col.s32.s8.s8.s32 "
                "{%0,%1,%2,%3}, {%4,%5,%6,%7}, {%8,%9}, {%0,%1,%2,%3};"
                : "+r"(acc[nt][0]), "+r"(acc[nt][1]), "+r"(acc[nt][2]), "+r"(acc[nt][3])
                : "r"(a0), "r"(a1), "r"(a2), "r"(a3), "r"(b0), "r"(b1));
        }
    }

    float shA = shS[m0 + r], shB = shS[m0 + r + 8];
    float sA = 0.f, sB = 0.f;
    #pragma unroll
    for (int nt = 0; nt < 16; ++nt) {
        int j0 = nh*128 + nt*8 + 2*c;
        float sj0 = smjS[j0], sj1 = smjS[j0 + 1];
        float m0b = mbjS[j0], m1b = mbjS[j0 + 1];
        float e00 = __expf((float)acc[nt][0] * (shA*sj0) + m0b);
        float e01 = __expf((float)acc[nt][1] * (shA*sj1) + m1b);
        float e10 = __expf((float)acc[nt][2] * (shB*sj0) + m0b);
        float e11 = __expf((float)acc[nt][3] * (shB*sj1) + m1b);
        sA += e00 + e01;  sB += e10 + e11;
        acc[nt][0] = __float_as_int(e00);
        acc[nt][1] = __float_as_int(e01);
        acc[nt][2] = __float_as_int(e10);
        acc[nt][3] = __float_as_int(e11);
    }
    sA += __shfl_xor_sync(0xffffffffu, sA, 1);
    sA += __shfl_xor_sync(0xffffffffu, sA, 2);
    sB += __shfl_xor_sync(0xffffffffu, sB, 1);
    sB += __shfl_xor_sync(0xffffffffu, sB, 2);
    if (c == 0) {
        rs[nh*64 + m0 + r] = sA;
        rs[nh*64 + m0 + r + 8] = sB;
    }
    __syncthreads();
    float invA = 1.f / (rs[m0 + r] + rs[64 + m0 + r]);
    float invB = 1.f / (rs[m0 + r + 8] + rs[64 + m0 + r + 8]);

    signed char* dpA = g_D8 + (size_t)(B0 + m0 + r)*65536 + icol*256;
    signed char* dpB = g_D8 + (size_t)(B0 + m0 + r + 8)*65536 + icol*256;
    const float qsc = 1.f / FS_D;
    #pragma unroll
    for (int nt = 0; nt < 16; ++nt) {
        int j0 = nh*128 + nt*8 + 2*c;
        float pA0 = __int_as_float(acc[nt][0]) * invA;
        float pA1 = __int_as_float(acc[nt][1]) * invA;
        float pB0 = __int_as_float(acc[nt][2]) * invB;
        float pB1 = __int_as_float(acc[nt][3]) * invB;
        int qa0 = min(127, max(-127, __float2int_rn(fmaf(pA0, 256.f, -1.f) * qsc)));
        int qa1 = min(127, max(-127, __float2int_rn(fmaf(pA1, 256.f, -1.f) * qsc)));
        int qb0 = min(127, max(-127, __float2int_rn(fmaf(pB0, 256.f, -1.f) * qsc)));
        int qb1 = min(127, max(-127, __float2int_rn(fmaf(pB1, 256.f, -1.f) * qsc)));
        *(char2*)(dpA + j0) = make_char2((signed char)qa0, (signed char)qa1);
        *(char2*)(dpB + j0) = make_char2((signed char)qb0, (signed char)qb1);
        float pm0 = pA0 + pB0, pm1 = pA1 + pB1;
        pm0 += __shfl_xor_sync(0xffffffffu, pm0, 4);
        pm0 += __shfl_xor_sync(0xffffffffu, pm0, 8);
        pm0 += __shfl_xor_sync(0xffffffffu, pm0, 16);
        pm1 += __shfl_xor_sync(0xffffffffu, pm1, 4);
        pm1 += __shfl_xor_sync(0xffffffffu, pm1, 8);
        pm1 += __shfl_xor_sync(0xffffffffu, pm1, 16);
        if (r == 0) {
            psum[w*256 + j0] = pm0;
            psum[w*256 + j0 + 1] = pm1;
        }
    }
    __syncthreads();
    float s2 = 0.f;
    #pragma unroll
    for (int g = 0; g < 8; g++) s2 += psum[g*256 + t];
    atomicAdd(&out[OUT_PI + icol*256 + t], s2 * (1.f/512.f));
}

// ---------- K1: g_hsum += x @ W1 chunk (tile 128x128, 32 k-splits, atomics) ----------
__global__ __launch_bounds__(256) void k1(const float* __restrict__ x,
                                          const float* __restrict__ W1) {
    __shared__ __align__(16) float sa[16*132];
    __shared__ __align__(16) float sw[16*128];
    int t = threadIdx.x, rg = t >> 4, cg = t & 15;
    int B0 = blockIdx.x * 128, kz = blockIdx.y;
    float acc[8][8] = {};
    for (int kt = 0; kt < 8; ++kt) {
        int k0 = kz*128 + kt*16;
        #pragma unroll
        for (int i = t; i < 512; i += 256) {
            int r = i >> 2, kq = i & 3;
            float4 v = *(const float4*)&x[(size_t)(B0 + r)*4096 + k0 + kq*4];
            sa[(kq*4+0)*132 + r] = v.x;
            sa[(kq*4+1)*132 + r] = v.y;
            sa[(kq*4+2)*132 + r] = v.z;
            sa[(kq*4+3)*132 + r] = v.w;
        }
        #pragma unroll
        for (int i = t; i < 512; i += 256) {
            int kk = i >> 5, c4 = i & 31;
            *(float4*)&sw[kk*128 + c4*4] =
                *(const float4*)&W1[(size_t)(k0 + kk)*128 + c4*4];
        }
        __syncthreads();
        #pragma unroll
        for (int kk = 0; kk < 16; ++kk) {
            float4 a0 = *(const float4*)&sa[kk*132 + rg*8];
            float4 a1 = *(const float4*)&sa[kk*132 + rg*8 + 4];
            float4 b0 = *(const float4*)&sw[kk*128 + cg*8];
            float4 b1 = *(const float4*)&sw[kk*128 + cg*8 + 4];
            float av[8] = {a0.x,a0.y,a0.z,a0.w,a1.x,a1.y,a1.z,a1.w};
            float bv[8] = {b0.x,b0.y,b0.z,b0.w,b1.x,b1.y,b1.z,b1.w};
            #pragma unroll
            for (int i = 0; i < 8; i++)
                #pragma unroll
                for (int q = 0; q < 8; q++)
                    acc[i][q] = fmaf(av[i], bv[q], acc[i][q]);
        }
        __syncthreads();
    }
    #pragma unroll
    for (int i = 0; i < 8; i++) {
        int r = B0 + rg*8 + i;
        #pragma unroll
        for (int q = 0; q < 8; q++)
            atomicAdd(&g_hsum[r*128 + cg*8 + q], acc[i][q]);
    }
}

// ---------- K5: fused param head + RK4 SEIR sim (register int8 D + DP4A) ----------
__global__ __launch_bounds__(256, 2) void k5(const float* __restrict__ x,
                                             const float* __restrict__ b1,
                                             const float* __restrict__ W2,
                                             const float* __restrict__ b2,
                                             float* __restrict__ out) {
    __shared__ float red[2][8];
    __shared__ __align__(16) unsigned Ipk[2][64];
    __shared__ float hrow[128];
    int t = threadIdx.x, b = blockIdx.x;
    int lane = t & 31, warp = t >> 5;

    // --- param head: h = relu(hsum+b1); 4 sigmoid dots (same k-order as old k2f) ---
    if (t < 128) hrow[t] = fmaxf(g_hsum[b*128 + t] + b1[t], 0.f);
    __syncthreads();
    float d0 = 0.f, d1 = 0.f, d2 = 0.f, d3 = 0.f;
    #pragma unroll 4
    for (int k = 0; k < 128; ++k) {
        float hv = hrow[k];
        const float* wr = W2 + (size_t)k*1024;
        d0 = fmaf(hv, __ldg(wr + t), d0);
        d1 = fmaf(hv, __ldg(wr + 256 + t), d1);
        d2 = fmaf(hv, __ldg(wr + 512 + t), d2);
        d3 = fmaf(hv, __ldg(wr + 768 + t), d3);
    }
    float beta = 3.f / (1.f + __expf(-(d0 + b2[t])));
    float sg   = 1.f / (1.f + __expf(-(d1 + b2[256 + t])));
    float gm   = 1.f / (1.f + __expf(-(d2 + b2[512 + t])));
    float e0r  = 5.f / (1.f + __expf(-(d3 + b2[768 + t])));
    atomicAdd(&out[OUT_BM + t],       beta * (1.f/512.f));
    atomicAdd(&out[OUT_BM + 256 + t], sg   * (1.f/512.f));
    atomicAdd(&out[OUT_BM + 512 + t], gm   * (1.f/512.f));

    // --- D column gather (coalesced) + consistent colsum via dp4a-with-ones ---
    unsigned qw[64];
    int Cq = 0;
    {
        const signed char* Ds = g_D8 + (size_t)b*65536 + t;
        #pragma unroll
        for (int g = 0; g < 64; ++g) {
            int b0 = (int)__ldg(Ds + (size_t)(g*4 + 0)*256);
            int b1v = (int)__ldg(Ds + (size_t)(g*4 + 1)*256);
            int b2v = (int)__ldg(Ds + (size_t)(g*4 + 2)*256);
            int b3 = (int)__ldg(Ds + (size_t)(g*4 + 3)*256);
            unsigned w = (unsigned)(b0 & 255) | ((unsigned)(b1v & 255) << 8) |
                         ((unsigned)(b2v & 255) << 16) | ((unsigned)(b3 & 255) << 24);
            qw[g] = w;
            Cq = __dp4a((int)w, 0x01010101, Cq);
        }
    }
    float Cm = (float)Cq * FS_D;
    const float fscale = FS_D * (1.f/127.f);

    float I = fmaxf(x[(size_t)b*4096 + 15*256 + t], 1e-6f);
    float E = I * e0r;
    float S = fmaxf(1.f - E - I, 0.01f);

    int ec = 0;
    auto force = [&](float Iv) -> float {
        int buf = ec & 1;  ec ^= 1;
        ((signed char*)Ipk[buf])[t] = (signed char)__float2int_rn((Iv - 0.5f) * 127.f);
        float s = Iv;
        #pragma unroll
        for (int o = 16; o > 0; o >>= 1) s += __shfl_xor_sync(0xffffffffu, s, o);
        if (lane == 0) red[buf][warp] = s;
        __syncthreads();
        float sumI = red[buf][0]+red[buf][1]+red[buf][2]+red[buf][3]
                   + red[buf][4]+red[buf][5]+red[buf][6]+red[buf][7];
        int a0 = 0, a1 = 0, a2 = 0, a3 = 0;
        const unsigned* ip = Ipk[buf];
        #pragma unroll
        for (int g = 0; g < 64; g += 4) {
            uint4 wv = *(const uint4*)&ip[g];
            a0 = __dp4a((int)wv.x, (int)qw[g+0], a0);
            a1 = __dp4a((int)wv.y, (int)qw[g+1], a1);
            a2 = __dp4a((int)wv.z, (int)qw[g+2], a2);
            a3 = __dp4a((int)wv.w, (int)qw[g+3], a3);
        }
        float resid = (float)(a0 + a1 + a2 + a3) * fscale;
        return (sumI + 0.5f * Cm + resid) * (1.f/256.f);
    };

    for (int w = 0; w < HOR; ++w) {
        for (int st = 0; st < 4; ++st) {
            float f1 = force(I);
            float ni = beta * S * f1;
            float dS1 = -ni, dE1 = ni - sg*E, dI1 = sg*E - gm*I;
            float S2 = S + 0.125f*dS1, E2 = E + 0.125f*dE1, I2 = I + 0.125f*dI1;
            float f2 = force(I2); ni = beta * S2 * f2;
            float dS2 = -ni, dE2 = ni - sg*E2, dI2 = sg*E2 - gm*I2;
            float S3 = S + 0.125f*dS2, E3 = E + 0.125f*dE2, I3 = I + 0.125f*dI2;
            float f3 = force(I3); ni = beta * S3 * f3;
            float dS3 = -ni, dE3 = ni - sg*E3, dI3 = sg*E3 - gm*I3;
            float S4 = S + 0.25f*dS3, E4 = E + 0.25f*dE3, I4 = I + 0.25f*dI3;
            float f4 = force(I4); ni = beta * S4 * f4;
            float dS4 = -ni, dE4 = ni - sg*E4, dI4 = sg*E4 - gm*I4;
            const float c = 0.25f / 6.f;
            S = fminf(fmaxf(S + c*(dS1 + 2.f*dS2 + 2.f*dS3 + dS4), 0.f), 1.f);
            E = fminf(fmaxf(E + c*(dE1 + 2.f*dE2 + 2.f*dE3 + dE4), 0.f), 1.f);
            I = fminf(fmaxf(I + c*(dI1 + 2.f*dI2 + 2.f*dI3 + dI4), 0.f), 1.f);
        }
        out[OUT_I + ((size_t)b*HOR + w)*256 + t] = I;
        out[OUT_E + ((size_t)b*HOR + w)*256 + t] = E;
    }
}

extern "C" void kernel_launch(void* const* d_in, const int* in_sizes, int n_in,
                              void* d_out, int out_size) {
    const float* x    = (const float*)d_in[0];
    const float* cnn  = (const float*)d_in[1];
    const float* W1   = (const float*)d_in[2];
    const float* b1   = (const float*)d_in[3];
    const float* W2   = (const float*)d_in[4];
    const float* b2   = (const float*)d_in[5];
    const float* M1   = (const float*)d_in[6];
    const float* mb1  = (const float*)d_in[7];
    const float* M2   = (const float*)d_in[8];
    const float* mb2  = (const float*)d_in[9];
    float* out = (float*)d_out;

    static cudaStream_t s2 = nullptr;
    static cudaEvent_t evA = nullptr, evK1 = nullptr;
    if (!s2) {
        cudaStreamCreateWithFlags(&s2, cudaStreamNonBlocking);
        cudaEventCreateWithFlags(&evA, cudaEventDisableTiming);
        cudaEventCreateWithFlags(&evK1, cudaEventDisableTiming);
        cudaFuncSetAttribute(k4, cudaFuncAttributeMaxDynamicSharedMemorySize, K4_SMEM);
    }

    // launch 1 (s0): fused zero + M2 quant + mobility hidden quant
    kA<<<264, 256>>>(M2, cnn, M1, mb1, out);
    cudaEventRecord(evA, 0);

    // launch 2 (s0): IMMA softmax + int8 D (in-order after kA)
    k4<<<dim3(256, 8), 256, K4_SMEM>>>(mb2, out);

    // launch 3 (s2): param GEMM split-k (needs kA's g_hsum zeroing)
    cudaStreamWaitEvent(s2, evA, 0);
    k1<<<dim3(4, 32), 256, 0, s2>>>(x, W1);
    cudaEventRecord(evK1, s2);

    // launch 4 (s0): fused param head + sim (after k4 in-order, + k1 via event)
    cudaStreamWaitEvent(0, evK1, 0);
    k5<<<512, 256>>>(x, b1, W2, b2, out);
}